// round 9
// baseline (speedup 1.0000x reference)
#include <cuda_runtime.h>
#include <cstdint>

// Masked mean over first xs_len[b] rows of xs[b]: out[b][d] = sum_{s<L} xs[b][s][d] / L
// xs: [16, 4096, 512] f32, xs_len: [16] (int32 OR int64 -- decoded at runtime), out: [16, 512] f32

#define B 16
#define S 4096
#define D 512
#define D4 (D / 4)                   // 128 float4 per row
#define SPLIT 32
#define ROWS_PER_SPLIT (S / SPLIT)   // 128

// Scratch partials: [B][SPLIT][D4] float4 = 1 MiB. Only splits with s0 < L are
// written; finalize reads exactly those (n_valid) -> deterministic.
__device__ float4 g_partial[B * SPLIT * D4];

// Robust length decode: int64 value lies in [1, S]; an int32 buffer read as
// int64 packs two lengths (both >= 1) and falls outside [1, S].
__device__ __forceinline__ int decode_len(const void* xs_len, int b) {
    long long v64 = ((const long long*)xs_len)[b];
    if (v64 >= 1 && v64 <= (long long)S) return (int)v64;
    return ((const int*)xs_len)[b];
}

// K1: grid (SPLIT, B), 512 threads. Threads arranged as (quarter, col):
//   col = t & 127  -> float4 column
//   q   = t >> 7   -> rows s0+q, s0+q+4, ... (stride 4)
// Each quarter accumulates up to 32 rows (unroll 8 -> 8 LDG.128 in flight per
// thread), then a 4-way shared-memory fold produces the split partial.
__global__ void __launch_bounds__(512, 3)
mean_partial_kernel(const float* __restrict__ xs,
                    const void* __restrict__ xs_len) {
    const int sp  = blockIdx.x;
    const int b   = blockIdx.y;
    const int t   = threadIdx.x;
    const int col = t & (D4 - 1);
    const int q   = t >> 7;

    const int L  = decode_len(xs_len, b);
    const int s0 = sp * ROWS_PER_SPLIT;
    if (s0 >= L) return;                 // uniform per block: no partial written
    int s1 = s0 + ROWS_PER_SPLIT;
    if (s1 > L) s1 = L;

    const float4* __restrict__ base =
        reinterpret_cast<const float4*>(xs + (size_t)b * S * D) + col;

    float4 acc = make_float4(0.f, 0.f, 0.f, 0.f);

    int s = s0 + q;
    // 8 independent loads in flight (rows s, s+4, ..., s+28)
    for (; s + 28 < s1; s += 32) {
        float4 v0 = base[(size_t)(s +  0) * D4];
        float4 v1 = base[(size_t)(s +  4) * D4];
        float4 v2 = base[(size_t)(s +  8) * D4];
        float4 v3 = base[(size_t)(s + 12) * D4];
        float4 v4 = base[(size_t)(s + 16) * D4];
        float4 v5 = base[(size_t)(s + 20) * D4];
        float4 v6 = base[(size_t)(s + 24) * D4];
        float4 v7 = base[(size_t)(s + 28) * D4];
        acc.x += (v0.x + v1.x) + (v2.x + v3.x) + (v4.x + v5.x) + (v6.x + v7.x);
        acc.y += (v0.y + v1.y) + (v2.y + v3.y) + (v4.y + v5.y) + (v6.y + v7.y);
        acc.z += (v0.z + v1.z) + (v2.z + v3.z) + (v4.z + v5.z) + (v6.z + v7.z);
        acc.w += (v0.w + v1.w) + (v2.w + v3.w) + (v4.w + v5.w) + (v6.w + v7.w);
    }
    for (; s < s1; s += 4) {
        float4 v = base[(size_t)s * D4];
        acc.x += v.x; acc.y += v.y; acc.z += v.z; acc.w += v.w;
    }

    __shared__ float4 sm[512];
    sm[t] = acc;
    __syncthreads();

    if (q == 0) {
        float4 a = sm[t + 128];
        float4 bq = sm[t + 256];
        float4 c = sm[t + 384];
        acc.x += (a.x + bq.x) + c.x;
        acc.y += (a.y + bq.y) + c.y;
        acc.z += (a.z + bq.z) + c.z;
        acc.w += (a.w + bq.w) + c.w;
        g_partial[(b * SPLIT + sp) * D4 + col] = acc;
    }
}

// K2: grid B*16 CTAs, 128 threads. CTA (b, g) covers float4 cols [g*8, g*8+8).
//   t = sp_grp*8 + c : sp_grp in [0,16) sums up to 2 valid splits; c in [0,8).
// Only splits k < n_valid = ceil(L/128) are read. Fixed-order 16-way smem fold.
__global__ void __launch_bounds__(128)
mean_finalize_kernel(const void* __restrict__ xs_len,
                     float* __restrict__ out) {
    const int b = blockIdx.x >> 4;      // batch
    const int g = blockIdx.x & 15;      // column group: float4 cols [g*8, g*8+8)
    const int t = threadIdx.x;
    const int sp_grp = t >> 3;          // [0,16): which 2-split chunk
    const int c      = t & 7;           // [0,8): float4 column within group

    const int L = decode_len(xs_len, b);
    const int n_valid = (L + ROWS_PER_SPLIT - 1) / ROWS_PER_SPLIT;  // [1,32]

    const int col4 = g * 8 + c;
    const float4* __restrict__ base = &g_partial[(size_t)b * SPLIT * D4 + col4];

    float4 acc = make_float4(0.f, 0.f, 0.f, 0.f);
#pragma unroll
    for (int k = 0; k < 2; k++) {
        int sp = sp_grp * 2 + k;
        if (sp < n_valid) {
            float4 v = base[(size_t)sp * D4];
            acc.x += v.x; acc.y += v.y; acc.z += v.z; acc.w += v.w;
        }
    }

    __shared__ float4 sm[128];
    sm[t] = acc;
    __syncthreads();

    if (t < 8) {
        float4 r = sm[t];
#pragma unroll
        for (int k = 1; k < 16; k++) {
            float4 v = sm[t + 8 * k];
            r.x += v.x; r.y += v.y; r.z += v.z; r.w += v.w;
        }
        const float inv = 1.0f / (float)L;
        r.x *= inv; r.y *= inv; r.z *= inv; r.w *= inv;
        reinterpret_cast<float4*>(out)[b * D4 + g * 8 + t] = r;
    }
}

extern "C" void kernel_launch(void* const* d_in, const int* in_sizes, int n_in,
                              void* d_out, int out_size) {
    const float* xs = (const float*)d_in[0];
    const void* xs_len = d_in[1];
    float* out = (float*)d_out;

    dim3 grid1(SPLIT, B);
    mean_partial_kernel<<<grid1, 512>>>(xs, xs_len);
    mean_finalize_kernel<<<B * 16, 128>>>(xs_len, out);
}

// round 10
// speedup vs baseline: 1.1726x; 1.1726x over previous
#include <cuda_runtime.h>
#include <cstdint>

// Masked mean over first xs_len[b] rows of xs[b]: out[b][d] = sum_{s<L} xs[b][s][d] / L
// xs: [16, 4096, 512] f32, xs_len: [16] (int32 OR int64 -- decoded at runtime), out: [16, 512] f32

#define B 16
#define S 4096
#define D 512
#define D4 (D / 4)                   // 128 float4 per row
#define SPLIT 64
#define ROWS_PER_SPLIT (S / SPLIT)   // 64

// Scratch partials: [B][SPLIT][D4] float4 = 2 MiB. Only splits with s0 < L are
// written; finalize reads exactly those (n_valid) -> deterministic.
__device__ float4 g_partial[B * SPLIT * D4];

// Robust length decode: int64 value lies in [1, S]; an int32 buffer read as
// int64 packs two lengths (both >= 1) and falls outside [1, S].
__device__ __forceinline__ int decode_len(const void* xs_len, int b) {
    long long v64 = ((const long long*)xs_len)[b];
    if (v64 >= 1 && v64 <= (long long)S) return (int)v64;
    return ((const int*)xs_len)[b];
}

// K1: grid (SPLIT, B), 256 threads. Threads arranged as (half, col):
//   col  = t & 127  -> float4 column
//   half = t >> 7   -> rows s0+half, s0+half+2, ... (stride 2)
// Each half accumulates up to 32 rows (unroll 8 -> 8 LDG.128 in flight per
// thread), then a 2-way shared-memory fold produces the split partial.
__global__ void __launch_bounds__(256, 6)
mean_partial_kernel(const float* __restrict__ xs,
                    const void* __restrict__ xs_len) {
    const int sp   = blockIdx.x;
    const int b    = blockIdx.y;
    const int t    = threadIdx.x;
    const int col  = t & (D4 - 1);
    const int half = t >> 7;

    const int L  = decode_len(xs_len, b);
    const int s0 = sp * ROWS_PER_SPLIT;
    if (s0 >= L) return;                 // uniform per block: no partial written
    int s1 = s0 + ROWS_PER_SPLIT;
    if (s1 > L) s1 = L;

    const float4* __restrict__ base =
        reinterpret_cast<const float4*>(xs + (size_t)b * S * D) + col;

    float4 acc = make_float4(0.f, 0.f, 0.f, 0.f);

    int s = s0 + half;
    // 8 independent loads in flight (rows s, s+2, ..., s+14)
    for (; s + 14 < s1; s += 16) {
        float4 v0 = base[(size_t)(s +  0) * D4];
        float4 v1 = base[(size_t)(s +  2) * D4];
        float4 v2 = base[(size_t)(s +  4) * D4];
        float4 v3 = base[(size_t)(s +  6) * D4];
        float4 v4 = base[(size_t)(s +  8) * D4];
        float4 v5 = base[(size_t)(s + 10) * D4];
        float4 v6 = base[(size_t)(s + 12) * D4];
        float4 v7 = base[(size_t)(s + 14) * D4];
        acc.x += (v0.x + v1.x) + (v2.x + v3.x) + (v4.x + v5.x) + (v6.x + v7.x);
        acc.y += (v0.y + v1.y) + (v2.y + v3.y) + (v4.y + v5.y) + (v6.y + v7.y);
        acc.z += (v0.z + v1.z) + (v2.z + v3.z) + (v4.z + v5.z) + (v6.z + v7.z);
        acc.w += (v0.w + v1.w) + (v2.w + v3.w) + (v4.w + v5.w) + (v6.w + v7.w);
    }
    for (; s < s1; s += 2) {
        float4 v = base[(size_t)s * D4];
        acc.x += v.x; acc.y += v.y; acc.z += v.z; acc.w += v.w;
    }

    __shared__ float4 sm[256];
    sm[t] = acc;
    __syncthreads();

    if (half == 0) {
        float4 o = sm[t + 128];
        acc.x += o.x; acc.y += o.y; acc.z += o.z; acc.w += o.w;
        g_partial[(b * SPLIT + sp) * D4 + col] = acc;
    }
}

// K2: grid B*16 CTAs, 128 threads. CTA (b, g) covers float4 cols [g*8, g*8+8).
//   t = sp_grp*8 + c : sp_grp in [0,16) sums up to 4 valid splits; c in [0,8).
// Only splits k < n_valid = ceil(L/64) are read. Fixed-order 16-way smem fold.
__global__ void __launch_bounds__(128)
mean_finalize_kernel(const void* __restrict__ xs_len,
                     float* __restrict__ out) {
    const int b = blockIdx.x >> 4;      // batch
    const int g = blockIdx.x & 15;      // column group: float4 cols [g*8, g*8+8)
    const int t = threadIdx.x;
    const int sp_grp = t >> 3;          // [0,16): which 4-split chunk
    const int c      = t & 7;           // [0,8): float4 column within group

    const int L = decode_len(xs_len, b);
    const int n_valid = (L + ROWS_PER_SPLIT - 1) / ROWS_PER_SPLIT;  // [1,64]

    const int col4 = g * 8 + c;
    const float4* __restrict__ base = &g_partial[(size_t)b * SPLIT * D4 + col4];

    float4 acc = make_float4(0.f, 0.f, 0.f, 0.f);
#pragma unroll
    for (int k = 0; k < 4; k++) {
        int sp = sp_grp * 4 + k;
        if (sp < n_valid) {
            float4 v = base[(size_t)sp * D4];
            acc.x += v.x; acc.y += v.y; acc.z += v.z; acc.w += v.w;
        }
    }

    __shared__ float4 sm[128];
    sm[t] = acc;
    __syncthreads();

    if (t < 8) {
        float4 r = sm[t];
#pragma unroll
        for (int k = 1; k < 16; k++) {
            float4 v = sm[t + 8 * k];
            r.x += v.x; r.y += v.y; r.z += v.z; r.w += v.w;
        }
        const float inv = 1.0f / (float)L;
        r.x *= inv; r.y *= inv; r.z *= inv; r.w *= inv;
        reinterpret_cast<float4*>(out)[b * D4 + g * 8 + t] = r;
    }
}

extern "C" void kernel_launch(void* const* d_in, const int* in_sizes, int n_in,
                              void* d_out, int out_size) {
    const float* xs = (const float*)d_in[0];
    const void* xs_len = d_in[1];
    float* out = (float*)d_out;

    dim3 grid1(SPLIT, B);
    mean_partial_kernel<<<grid1, 256>>>(xs, xs_len);
    mean_finalize_kernel<<<B * 16, 128>>>(xs_len, out);
}